// round 13
// baseline (speedup 1.0000x reference)
#include <cuda_runtime.h>
#include <cuda_bf16.h>

#define N_ATOM 131072
#define E_ATOM 524288
#define N_FRAG 32768
#define E_FRAG 131072
#define HID 256
#define HID4 64
#define FEAT 9

// ================= device scratch (no allocs allowed) ========================
__device__ float g_tmpA[(size_t)N_ATOM * HID];  // atom-sized GEMM output
__device__ float g_tmpF[(size_t)N_FRAG * HID];  // pooled alpha*xa / frag GEMM out
__device__ float g_xf[(size_t)N_FRAG * HID];    // frag input projection (fp32)
__device__ float g_ewA[E_ATOM];
__device__ float g_degA[N_ATOM];
__device__ float g_ewF[E_FRAG];
__device__ float g_degF[N_FRAG];
__device__ float g_cnt[N_FRAG];
__device__ float g_salpha[N_FRAG];              // sum of alpha per frag
// bf16x3 split operand buffers
__device__ __nv_bfloat16 g_ah[(size_t)N_ATOM * HID];
__device__ __nv_bfloat16 g_am[(size_t)N_ATOM * HID];
__device__ __nv_bfloat16 g_fh[(size_t)N_FRAG * HID];
__device__ __nv_bfloat16 g_fm[(size_t)N_FRAG * HID];
__device__ __nv_bfloat16 g_ph[(size_t)N_FRAG * HID];   // pooled split hi
__device__ __nv_bfloat16 g_pm[(size_t)N_FRAG * HID];   // pooled split mid
// transposed+split weights: [4][256][256] (0=Wg1, 1=Wa2f, 2=Wg2, 3=Wf2a)
__device__ __nv_bfloat16 g_wth[4 * HID * HID];
__device__ __nv_bfloat16 g_wtm[4 * HID * HID];

// ================= PTX helpers ===============================================
__device__ __forceinline__ void red_add_v4(float* addr, float4 v) {
    asm volatile("red.global.add.v4.f32 [%0], {%1, %2, %3, %4};"
                 :: "l"(addr), "f"(v.x), "f"(v.y), "f"(v.z), "f"(v.w)
                 : "memory");
}
__device__ __forceinline__ unsigned smem_u32(const void* p) {
    unsigned a;
    asm("{ .reg .u64 t; cvta.to.shared.u64 t, %1; cvt.u32.u64 %0, t; }"
        : "=r"(a) : "l"(p));
    return a;
}
#define LDSM4(r, addr) \
    asm volatile("ldmatrix.sync.aligned.m8n8.x4.shared.b16 {%0,%1,%2,%3}, [%4];" \
        : "=r"((r)[0]), "=r"((r)[1]), "=r"((r)[2]), "=r"((r)[3]) : "r"(addr))

#define MMA16816(c, a, b0, b1) \
    asm volatile("mma.sync.aligned.m16n8k16.row.col.f32.bf16.bf16.f32 " \
        "{%0,%1,%2,%3}, {%4,%5,%6,%7}, {%8,%9}, {%0,%1,%2,%3};" \
        : "+f"((c)[0]), "+f"((c)[1]), "+f"((c)[2]), "+f"((c)[3]) \
        : "r"((a)[0]), "r"((a)[1]), "r"((a)[2]), "r"((a)[3]), "r"(b0), "r"(b1))

static __device__ __forceinline__ unsigned sw128(unsigned b) {
    return b ^ ((b >> 3) & 0x70);
}

__device__ __forceinline__ void split2(float x, __nv_bfloat16& h, __nv_bfloat16& m) {
    h = __float2bfloat16_rn(x);
    m = __float2bfloat16_rn(x - __bfloat162float(h));
}

// ============ mma.sync bf16x3 GEMM: C[M,256] = A[M,256] @ W[256,256] =========
// A-stationary: one block per 64-row band computes FULL N=256 width.
// MODE 0: C = A@W                (SELF 1: also Cacc = C / deg[row])
// MODE 1: C = A@W + bias
// MODE 3: frag combine: v = (A@W + salpha[row]*bias)/max(cnt,1) + xf[row,:];
//         split v -> oh/om (bf16). alpha slot = salpha, deg slot = cnt,
//         Cacc slot = xf. No fp32 C write.
template <int MODE, int SELF>
__global__ __launch_bounds__(256, 2) void gemm_mma(
    const __nv_bfloat16* __restrict__ Ahi, const __nv_bfloat16* __restrict__ Amid,
    const __nv_bfloat16* __restrict__ Bhi, const __nv_bfloat16* __restrict__ Bmid,
    const float* __restrict__ bias, const float* __restrict__ alpha,
    const float* __restrict__ deg, const int* __restrict__ a2f,
    float* __restrict__ Cacc, float* __restrict__ C,
    __nv_bfloat16* __restrict__ oh, __nv_bfloat16* __restrict__ om)
{
    __shared__ __align__(16) unsigned char sAh[64 * 128];
    __shared__ __align__(16) unsigned char sAm[64 * 128];
    __shared__ __align__(16) unsigned char sBh[128 * 128];
    __shared__ __align__(16) unsigned char sBm[128 * 128];

    int t = threadIdx.x, wid = t >> 5, lane = t & 31;
    int wm = wid & 1, wn = wid >> 1;
    int row0A = blockIdx.x * 64;

    unsigned uAh = smem_u32(sAh), uAm = smem_u32(sAm);
    unsigned uBh = smem_u32(sBh), uBm = smem_u32(sBm);

    int rl = lane & 15;
    unsigned cl = (lane & 16);

    float c[2][8][4];
#pragma unroll
    for (int i = 0; i < 2; i++)
#pragma unroll
        for (int j = 0; j < 8; j++)
#pragma unroll
            for (int q = 0; q < 4; q++) c[i][j][q] = 0.0f;

    auto load_B_half = [&](int half, int k0) {
#pragma unroll
        for (int i = 0; i < 4; i++) {
            int idx = i * 256 + t;
            int r = idx >> 3, c8 = idx & 7;
            unsigned sw = sw128((unsigned)(r * 128 + c8 * 16));
            *(float4*)(sBh + sw) =
                *(const float4*)(Bhi + (size_t)(half * 128 + r) * HID + k0 + c8 * 8);
            *(float4*)(sBm + sw) =
                *(const float4*)(Bmid + (size_t)(half * 128 + r) * HID + k0 + c8 * 8);
        }
    };

    auto compute_half = [&](int half) {
#pragma unroll
        for (int s = 0; s < 4; s++) {
            unsigned kb = s * 32;
            unsigned ah[2][4], am[2][4], bh[2][4], bm[2][4];
#pragma unroll
            for (int mt = 0; mt < 2; mt++) {
                unsigned off = sw128((unsigned)((wm * 32 + mt * 16 + rl) * 128) + kb + cl);
                LDSM4(ah[mt], uAh + off);
                LDSM4(am[mt], uAm + off);
            }
#pragma unroll
            for (int ng = 0; ng < 2; ng++) {
                unsigned off = sw128((unsigned)((wn * 32 + ng * 16 + rl) * 128) + kb + cl);
                LDSM4(bh[ng], uBh + off);
                LDSM4(bm[ng], uBm + off);
            }
#pragma unroll
            for (int mt = 0; mt < 2; mt++)
#pragma unroll
                for (int nt = 0; nt < 4; nt++) {
                    int ng = nt >> 1, sel = nt & 1;
                    float* acc = c[mt][half * 4 + nt];
                    MMA16816(acc, ah[mt], bh[ng][sel], bh[ng][sel + 2]);
                    MMA16816(acc, ah[mt], bm[ng][sel], bm[ng][sel + 2]);
                    MMA16816(acc, am[mt], bh[ng][sel], bh[ng][sel + 2]);
                }
        }
    };

#pragma unroll 1
    for (int ch = 0; ch < 4; ch++) {
        int k0 = ch * 64;
        __syncthreads();
#pragma unroll
        for (int i = 0; i < 2; i++) {
            int idx = i * 256 + t;
            int r = idx >> 3, c8 = idx & 7;
            unsigned sw = sw128((unsigned)(r * 128 + c8 * 16));
            *(float4*)(sAh + sw) =
                *(const float4*)(Ahi + (size_t)(row0A + r) * HID + k0 + c8 * 8);
            *(float4*)(sAm + sw) =
                *(const float4*)(Amid + (size_t)(row0A + r) * HID + k0 + c8 * 8);
        }
        load_B_half(0, k0);
        __syncthreads();
        compute_half(0);
        __syncthreads();
        load_B_half(1, k0);
        __syncthreads();
        compute_half(1);
    }

    // ---- epilogue ----
    int mwarp = row0A + wm * 32;
    int gc = (lane & 3) * 2;
#pragma unroll
    for (int mt = 0; mt < 2; mt++) {
#pragma unroll
        for (int h = 0; h < 2; h++) {
            int row = mwarp + mt * 16 + (lane >> 2) + h * 8;
            if (MODE == 3) {
                float sa = alpha[row];                      // salpha
                float invc = 1.0f / fmaxf(deg[row], 1.0f);  // cnt
#pragma unroll
                for (int half = 0; half < 2; half++)
#pragma unroll
                    for (int nt = 0; nt < 4; nt++) {
                        int col = half * 128 + wn * 32 + nt * 8 + gc;
                        float2 bb = *(const float2*)(bias + col);
                        float2 xv = *(const float2*)(Cacc + (size_t)row * HID + col);
                        float v0 = (c[mt][half * 4 + nt][h * 2 + 0] + sa * bb.x) * invc + xv.x;
                        float v1 = (c[mt][half * 4 + nt][h * 2 + 1] + sa * bb.y) * invc + xv.y;
                        __nv_bfloat16 h0, m0, h1, m1;
                        split2(v0, h0, m0); split2(v1, h1, m1);
                        *(__nv_bfloat162*)(oh + (size_t)row * HID + col) = __nv_bfloat162(h0, h1);
                        *(__nv_bfloat162*)(om + (size_t)row * HID + col) = __nv_bfloat162(m0, m1);
                    }
            } else {
                float d2 = 0.0f;
                if (SELF) d2 = 1.0f / deg[row];   // deg >= 1 always
#pragma unroll
                for (int half = 0; half < 2; half++)
#pragma unroll
                    for (int nt = 0; nt < 4; nt++) {
                        int col = half * 128 + wn * 32 + nt * 8 + gc;
                        float v0 = c[mt][half * 4 + nt][h * 2 + 0];
                        float v1 = c[mt][half * 4 + nt][h * 2 + 1];
                        if (MODE == 1) {
                            float2 bb = *(const float2*)(bias + col);
                            v0 += bb.x; v1 += bb.y;
                        }
                        *(float2*)(C + (size_t)row * HID + col) = make_float2(v0, v1);
                        if (SELF)
                            *(float2*)(Cacc + (size_t)row * HID + col) =
                                make_float2(v0 * d2, v1 * d2);
                    }
            }
        }
    }
}

// ======== weight prep (all 4 weights in one launch): Bt[n][k]=split(W[k][n]) =
__global__ void k_wprep(const float* __restrict__ Wg1, const float* __restrict__ Wa2f,
                        const float* __restrict__ Wg2, const float* __restrict__ Wf2a,
                        __nv_bfloat16* __restrict__ Bh, __nv_bfloat16* __restrict__ Bm)
{
    int n = blockIdx.x, k = threadIdx.x, w = blockIdx.y;
    const float* W = (w == 0) ? Wg1 : (w == 1) ? Wa2f : (w == 2) ? Wg2 : Wf2a;
    float x = W[k * HID + n];
    __nv_bfloat16 h, m;
    split2(x, h, m);
    Bh[w * HID * HID + n * HID + k] = h;
    Bm[w * HID * HID + n * HID + k] = m;
}

// ================= input projections =========================================
__global__ __launch_bounds__(HID) void k_atom_in(
    const float* __restrict__ x_atom, const float* __restrict__ W1,
    const float* __restrict__ b1, const float* __restrict__ s0,
    __nv_bfloat16* __restrict__ oh, __nv_bfloat16* __restrict__ om,
    float* __restrict__ degA)
{
    __shared__ float xs[FEAT];
    int r = blockIdx.x, h = threadIdx.x;
    if (h < FEAT) xs[h] = x_atom[r * FEAT + h];
    __syncthreads();
    float s = b1[h] + s0[(size_t)r * HID + h];
#pragma unroll
    for (int f = 0; f < FEAT; f++) s += xs[f] * W1[f * HID + h];
    __nv_bfloat16 hi, mi;
    split2(s, hi, mi);
    oh[(size_t)r * HID + h] = hi;
    om[(size_t)r * HID + h] = mi;
    if (h == 0) degA[r] = 1.0f;
}

__global__ __launch_bounds__(HID) void k_frag_in(
    const float* __restrict__ frag_h, const float* __restrict__ W2,
    const float* __restrict__ b2,
    float* __restrict__ xf, float* __restrict__ pooled,
    float* __restrict__ degF, float* __restrict__ cnt,
    float* __restrict__ salpha)
{
    __shared__ float xs[FEAT];
    int r = blockIdx.x, h = threadIdx.x;
    if (h < FEAT) xs[h] = frag_h[r * FEAT + h];
    __syncthreads();
    float s = b2[h];
#pragma unroll
    for (int f = 0; f < FEAT; f++) s += xs[f] * W2[f * HID + h];
    xf[(size_t)r * HID + h] = s;
    pooled[(size_t)r * HID + h] = 0.0f;
    if (h == 0) { degF[r] = 1.0f; cnt[r] = 0.0f; salpha[r] = 0.0f; }
}

// ================= per-frag atom counts (for scatter_mean) ===================
__global__ void k_cnt(const int* __restrict__ a2f, float* __restrict__ cnt, int n)
{
    int i = blockIdx.x * blockDim.x + threadIdx.x;
    if (i < n) atomicAdd(&cnt[a2f[i]], 1.0f);
}

// ================= edge prep =================================================
__global__ void k_edge_prep(const int* __restrict__ ei,
                            const float* __restrict__ raw,
                            float* __restrict__ ew, float* __restrict__ deg, int E)
{
    int e = blockIdx.x * blockDim.x + threadIdx.x;
    if (e >= E) return;
    float w = 1.0f / (1.0f + __expf(raw[e]));
    ew[e] = w;
    atomicAdd(&deg[ei[E + e]], w);
}

__global__ void k_rsqrt(float* __restrict__ deg, int n)
{
    int i = blockIdx.x * blockDim.x + threadIdx.x;
    if (i < n) deg[i] = rsqrtf(deg[i]);
}

// ================= GCN edge scatter (dst range [lo,hi) only) =================
__global__ __launch_bounds__(256) void k_scatter(
    const int* __restrict__ ei, const float* __restrict__ ew,
    const float* __restrict__ dinv, const float* __restrict__ xw,
    float* __restrict__ acc, int E, int dlo, int dhi)
{
    int e = blockIdx.x * 4 + (threadIdx.x >> 6);
    int j = threadIdx.x & 63;
    if (e >= E) return;
    int d = ei[E + e];
    if (d < dlo || d >= dhi) return;
    int s = ei[e];
    float nrm = dinv[s] * ew[e] * dinv[d];
    float4 v = ((const float4*)(xw + (size_t)s * HID))[j];
    v.x *= nrm; v.y *= nrm; v.z *= nrm; v.w *= nrm;
    red_add_v4(acc + (size_t)d * HID + (j << 2), v);
}

// acc = relu(acc + bias); POOL 0: emit split bf16 for next GEMM.
// POOL 1: instead red.add alpha*v into pooled[a2f[row]] and accumulate salpha
//         (split outputs skipped -- nothing consumes them).
template <int POOL>
__global__ void k_bias_relu(float* __restrict__ acc, const float* __restrict__ bias,
                            __nv_bfloat16* __restrict__ oh,
                            __nv_bfloat16* __restrict__ om,
                            const float* __restrict__ alpha,
                            const int* __restrict__ a2f,
                            float* __restrict__ pooled,
                            float* __restrict__ salpha, int n)
{
    int i = blockIdx.x * blockDim.x + threadIdx.x;
    if (i >= n * HID4) return;
    int r = i >> 6;
    float4 v = ((float4*)acc)[i];
    float4 b = ((const float4*)bias)[i & 63];
    v.x = fmaxf(v.x + b.x, 0.f); v.y = fmaxf(v.y + b.y, 0.f);
    v.z = fmaxf(v.z + b.z, 0.f); v.w = fmaxf(v.w + b.w, 0.f);
    ((float4*)acc)[i] = v;
    if (!POOL) {
        __nv_bfloat16 h0, m0, h1, m1, h2, m2, h3, m3;
        split2(v.x, h0, m0); split2(v.y, h1, m1);
        split2(v.z, h2, m2); split2(v.w, h3, m3);
        __nv_bfloat162* ph = (__nv_bfloat162*)(oh + (size_t)i * 4);
        __nv_bfloat162* pm = (__nv_bfloat162*)(om + (size_t)i * 4);
        ph[0] = __nv_bfloat162(h0, h1); ph[1] = __nv_bfloat162(h2, h3);
        pm[0] = __nv_bfloat162(m0, m1); pm[1] = __nv_bfloat162(m2, m3);
    } else {
        float al = alpha[r];
        int f = a2f[r];
        float4 pv = make_float4(v.x * al, v.y * al, v.z * al, v.w * al);
        red_add_v4(pooled + (size_t)f * HID + (i & 63) * 4, pv);
        if ((i & 63) == 0) atomicAdd(&salpha[f], al);
    }
}

// pooled fp32 -> split bf16 (GEMM2' input)
__global__ void k_split_pool(const float* __restrict__ pooled,
                             __nv_bfloat16* __restrict__ oh,
                             __nv_bfloat16* __restrict__ om, int n)
{
    int i = blockIdx.x * blockDim.x + threadIdx.x;
    if (i >= n * HID4) return;
    float4 v = ((const float4*)pooled)[i];
    __nv_bfloat16 h0, m0, h1, m1, h2, m2, h3, m3;
    split2(v.x, h0, m0); split2(v.y, h1, m1);
    split2(v.z, h2, m2); split2(v.w, h3, m3);
    __nv_bfloat162* ph = (__nv_bfloat162*)(oh + (size_t)i * 4);
    __nv_bfloat162* pm = (__nv_bfloat162*)(om + (size_t)i * 4);
    ph[0] = __nv_bfloat162(h0, h1); ph[1] = __nv_bfloat162(h2, h3);
    pm[0] = __nv_bfloat162(m0, m1); pm[1] = __nv_bfloat162(m2, m3);
}

// ================= frag -> atom broadcast ====================================
__global__ __launch_bounds__(256) void k_final(
    const int* __restrict__ a2f, const float* __restrict__ alpha,
    const float* __restrict__ xfp, float* __restrict__ xa, int n)
{
    int a = blockIdx.x * 4 + (threadIdx.x >> 6);
    int j = threadIdx.x & 63;
    if (a >= n) return;
    int f = a2f[a];
    float al = alpha[a];
    float4 v = ((float4*)(xa + (size_t)a * HID))[j];
    float4 p = ((const float4*)(xfp + (size_t)f * HID))[j];
    v.x += p.x * al; v.y += p.y * al; v.z += p.z * al; v.w += p.w * al;
    ((float4*)(xa + (size_t)a * HID))[j] = v;
}

// ================= host orchestration ========================================
extern "C" void kernel_launch(void* const* d_in, const int* in_sizes, int n_in,
                              void* d_out, int out_size)
{
    const float* x_atom  = (const float*)d_in[0];
    const int*   eiA     = (const int*)  d_in[1];
    const float* frag_h  = (const float*)d_in[2];
    const int*   eiF     = (const int*)  d_in[3];
    const int*   a2f     = (const int*)  d_in[4];
    const float* s0      = (const float*)d_in[5];
    const float* alpha   = (const float*)d_in[6];
    const float* curv    = (const float*)d_in[7];
    const float* fewraw  = (const float*)d_in[8];
    const float* W1      = (const float*)d_in[9];
    const float* b1      = (const float*)d_in[10];
    const float* W2      = (const float*)d_in[11];
    const float* b2      = (const float*)d_in[12];
    const float* Wg1     = (const float*)d_in[13];
    const float* bg1     = (const float*)d_in[14];
    const float* Wg2     = (const float*)d_in[15];
    const float* bg2     = (const float*)d_in[16];
    const float* Wa2f    = (const float*)d_in[17];
    const float* ba2f    = (const float*)d_in[18];
    const float* Wf2a    = (const float*)d_in[19];
    const float* bf2a    = (const float*)d_in[20];

    float* out_xa = (float*)d_out;
    float* out_xf = out_xa + (size_t)N_ATOM * HID;

    float *tmpA, *tmpF, *xf, *ewA, *degA, *ewF, *degF, *cnt, *salpha;
    __nv_bfloat16 *ah, *am, *fh, *fm, *ph, *pm, *wth, *wtm;
    cudaGetSymbolAddress((void**)&tmpA, g_tmpA);
    cudaGetSymbolAddress((void**)&tmpF, g_tmpF);
    cudaGetSymbolAddress((void**)&xf,   g_xf);
    cudaGetSymbolAddress((void**)&ewA,  g_ewA);
    cudaGetSymbolAddress((void**)&degA, g_degA);
    cudaGetSymbolAddress((void**)&ewF,  g_ewF);
    cudaGetSymbolAddress((void**)&degF, g_degF);
    cudaGetSymbolAddress((void**)&cnt,  g_cnt);
    cudaGetSymbolAddress((void**)&salpha, g_salpha);
    cudaGetSymbolAddress((void**)&ah,   g_ah);
    cudaGetSymbolAddress((void**)&am,   g_am);
    cudaGetSymbolAddress((void**)&fh,   g_fh);
    cudaGetSymbolAddress((void**)&fm,   g_fm);
    cudaGetSymbolAddress((void**)&ph,   g_ph);
    cudaGetSymbolAddress((void**)&pm,   g_pm);
    cudaGetSymbolAddress((void**)&wth,  g_wth);
    cudaGetSymbolAddress((void**)&wtm,  g_wtm);

    // --- launch order keeps GEMM1 at index 3 (ncu capture) ---
    // 0
    k_wprep<<<dim3(HID, 4), HID>>>(Wg1, Wa2f, Wg2, Wf2a, wth, wtm);
    // 1
    k_atom_in<<<N_ATOM, HID>>>(x_atom, W1, b1, s0, ah, am, degA);
    // 2
    k_edge_prep<<<E_ATOM / 256, 256>>>(eiA, curv, ewA, degA, E_ATOM);
    // 3: atom GCN GEMM [PROFILED]
    gemm_mma<0, 1><<<N_ATOM / 64, 256>>>(
        ah, am, wth, wtm, nullptr, nullptr, degA, nullptr, out_xa, tmpA,
        nullptr, nullptr);
    // 4
    k_rsqrt<<<N_ATOM / 256, 256>>>(degA, N_ATOM);
    // 5+6: dst-partitioned scatter (L2-resident accumulator half per pass)
    k_scatter<<<E_ATOM / 4, 256>>>(eiA, ewA, degA, tmpA, out_xa, E_ATOM,
                                   0, N_ATOM / 2);
    k_scatter<<<E_ATOM / 4, 256>>>(eiA, ewA, degA, tmpA, out_xa, E_ATOM,
                                   N_ATOM / 2, N_ATOM);
    // 7: frag input projection (zeroes pooled/cnt/salpha, seeds degF)
    k_frag_in<<<N_FRAG, HID>>>(frag_h, W2, b2, xf, tmpF, degF, cnt, salpha);
    // 8
    k_cnt<<<N_ATOM / 256, 256>>>(a2f, cnt, N_ATOM);
    // 9: relu+bias AND pooled += alpha * xa_relu (no dead split writes)
    k_bias_relu<1><<<N_ATOM * HID4 / 256, 256>>>(
        out_xa, bg1, nullptr, nullptr, alpha, a2f, tmpF, salpha, N_ATOM);
    // 10: pooled -> split bf16
    k_split_pool<<<N_FRAG * HID4 / 256, 256>>>(tmpF, ph, pm, N_FRAG);
    // 11: frag-sized projection GEMM; epilogue = /cnt + salpha*bias + xf, split
    gemm_mma<3, 0><<<N_FRAG / 64, 256>>>(
        ph, pm, wth + 1 * HID * HID, wtm + 1 * HID * HID, ba2f, salpha,
        cnt, nullptr, xf, nullptr, fh, fm);
    // 12
    k_edge_prep<<<E_FRAG / 256, 256>>>(eiF, fewraw, ewF, degF, E_FRAG);
    // 13: frag GCN GEMM
    gemm_mma<0, 1><<<N_FRAG / 64, 256>>>(
        fh, fm, wth + 2 * HID * HID, wtm + 2 * HID * HID, nullptr, nullptr,
        degF, nullptr, out_xf, tmpF, nullptr, nullptr);
    // 14
    k_rsqrt<<<N_FRAG / 256, 256>>>(degF, N_FRAG);
    // 15: frag scatter (33MB accumulator fits L2 -- single pass)
    k_scatter<<<E_FRAG / 4, 256>>>(eiF, ewF, degF, tmpF, out_xf, E_FRAG,
                                   0, N_FRAG);
    // 16
    k_bias_relu<0><<<N_FRAG * HID4 / 256, 256>>>(
        out_xf, bg2, fh, fm, nullptr, nullptr, nullptr, nullptr, N_FRAG);
    // 17
    gemm_mma<1, 0><<<N_FRAG / 64, 256>>>(
        fh, fm, wth + 3 * HID * HID, wtm + 3 * HID * HID, bf2a, nullptr,
        nullptr, nullptr, nullptr, tmpF, nullptr, nullptr);
    // 18
    k_final<<<N_ATOM / 4, 256>>>(a2f, alpha, tmpF, out_xa, N_ATOM);
}

// round 14
// speedup vs baseline: 1.1380x; 1.1380x over previous
#include <cuda_runtime.h>
#include <cuda_bf16.h>

#define N_ATOM 131072
#define E_ATOM 524288
#define N_FRAG 32768
#define E_FRAG 131072
#define HID 256
#define HID4 64
#define FEAT 9

// ================= device scratch (no allocs allowed) ========================
__device__ float g_tmpA[(size_t)N_ATOM * HID];  // atom-sized GEMM output
__device__ float g_tmpF[(size_t)N_FRAG * HID];  // pooled alpha*xa / frag GEMM out
__device__ float g_xf[(size_t)N_FRAG * HID];    // frag input projection (fp32)
__device__ float g_ewA[E_ATOM];
__device__ float g_degA[N_ATOM];
__device__ float g_ewF[E_FRAG];
__device__ float g_degF[N_FRAG];
__device__ float g_cnt[N_FRAG];
__device__ float g_salpha[N_FRAG];              // sum of alpha per frag
// bf16x3 split operand buffers
__device__ __nv_bfloat16 g_ah[(size_t)N_ATOM * HID];
__device__ __nv_bfloat16 g_am[(size_t)N_ATOM * HID];
__device__ __nv_bfloat16 g_fh[(size_t)N_FRAG * HID];
__device__ __nv_bfloat16 g_fm[(size_t)N_FRAG * HID];
__device__ __nv_bfloat16 g_ph[(size_t)N_FRAG * HID];   // pooled split hi
__device__ __nv_bfloat16 g_pm[(size_t)N_FRAG * HID];   // pooled split mid
// transposed+split weights: [4][256][256] (0=Wg1, 1=Wa2f, 2=Wg2, 3=Wf2a)
__device__ __nv_bfloat16 g_wth[4 * HID * HID];
__device__ __nv_bfloat16 g_wtm[4 * HID * HID];

// ================= PTX helpers ===============================================
__device__ __forceinline__ void red_add_v4(float* addr, float4 v) {
    asm volatile("red.global.add.v4.f32 [%0], {%1, %2, %3, %4};"
                 :: "l"(addr), "f"(v.x), "f"(v.y), "f"(v.z), "f"(v.w)
                 : "memory");
}
__device__ __forceinline__ unsigned smem_u32(const void* p) {
    unsigned a;
    asm("{ .reg .u64 t; cvta.to.shared.u64 t, %1; cvt.u32.u64 %0, t; }"
        : "=r"(a) : "l"(p));
    return a;
}
#define LDSM4(r, addr) \
    asm volatile("ldmatrix.sync.aligned.m8n8.x4.shared.b16 {%0,%1,%2,%3}, [%4];" \
        : "=r"((r)[0]), "=r"((r)[1]), "=r"((r)[2]), "=r"((r)[3]) : "r"(addr))

#define MMA16816(c, a, b0, b1) \
    asm volatile("mma.sync.aligned.m16n8k16.row.col.f32.bf16.bf16.f32 " \
        "{%0,%1,%2,%3}, {%4,%5,%6,%7}, {%8,%9}, {%0,%1,%2,%3};" \
        : "+f"((c)[0]), "+f"((c)[1]), "+f"((c)[2]), "+f"((c)[3]) \
        : "r"((a)[0]), "r"((a)[1]), "r"((a)[2]), "r"((a)[3]), "r"(b0), "r"(b1))

static __device__ __forceinline__ unsigned sw128(unsigned b) {
    return b ^ ((b >> 3) & 0x70);
}

__device__ __forceinline__ void split2(float x, __nv_bfloat16& h, __nv_bfloat16& m) {
    h = __float2bfloat16_rn(x);
    m = __float2bfloat16_rn(x - __bfloat162float(h));
}

// ============ mma.sync bf16x3 GEMM: C[M,256] = A[M,256] @ W[256,256] =========
// A-stationary: one block per 64-row band computes FULL N=256 width.
// MODE 0: C = A@W                (SELF 1: also Cacc = C / deg[row])
// MODE 1: C = A@W + bias
// MODE 3: frag combine: v = (A@W + salpha[row]*bias)/max(cnt,1) + xf[row,:];
//         split v -> oh/om (bf16). alpha slot = salpha, deg slot = cnt,
//         Cacc slot = xf. No fp32 C write.
template <int MODE, int SELF>
__global__ __launch_bounds__(256, 2) void gemm_mma(
    const __nv_bfloat16* __restrict__ Ahi, const __nv_bfloat16* __restrict__ Amid,
    const __nv_bfloat16* __restrict__ Bhi, const __nv_bfloat16* __restrict__ Bmid,
    const float* __restrict__ bias, const float* __restrict__ alpha,
    const float* __restrict__ deg, const int* __restrict__ a2f,
    float* __restrict__ Cacc, float* __restrict__ C,
    __nv_bfloat16* __restrict__ oh, __nv_bfloat16* __restrict__ om)
{
    __shared__ __align__(16) unsigned char sAh[64 * 128];
    __shared__ __align__(16) unsigned char sAm[64 * 128];
    __shared__ __align__(16) unsigned char sBh[128 * 128];
    __shared__ __align__(16) unsigned char sBm[128 * 128];

    int t = threadIdx.x, wid = t >> 5, lane = t & 31;
    int wm = wid & 1, wn = wid >> 1;
    int row0A = blockIdx.x * 64;

    unsigned uAh = smem_u32(sAh), uAm = smem_u32(sAm);
    unsigned uBh = smem_u32(sBh), uBm = smem_u32(sBm);

    int rl = lane & 15;
    unsigned cl = (lane & 16);

    float c[2][8][4];
#pragma unroll
    for (int i = 0; i < 2; i++)
#pragma unroll
        for (int j = 0; j < 8; j++)
#pragma unroll
            for (int q = 0; q < 4; q++) c[i][j][q] = 0.0f;

    auto load_B_half = [&](int half, int k0) {
#pragma unroll
        for (int i = 0; i < 4; i++) {
            int idx = i * 256 + t;
            int r = idx >> 3, c8 = idx & 7;
            unsigned sw = sw128((unsigned)(r * 128 + c8 * 16));
            *(float4*)(sBh + sw) =
                *(const float4*)(Bhi + (size_t)(half * 128 + r) * HID + k0 + c8 * 8);
            *(float4*)(sBm + sw) =
                *(const float4*)(Bmid + (size_t)(half * 128 + r) * HID + k0 + c8 * 8);
        }
    };

    auto compute_half = [&](int half) {
#pragma unroll
        for (int s = 0; s < 4; s++) {
            unsigned kb = s * 32;
            unsigned ah[2][4], am[2][4], bh[2][4], bm[2][4];
#pragma unroll
            for (int mt = 0; mt < 2; mt++) {
                unsigned off = sw128((unsigned)((wm * 32 + mt * 16 + rl) * 128) + kb + cl);
                LDSM4(ah[mt], uAh + off);
                LDSM4(am[mt], uAm + off);
            }
#pragma unroll
            for (int ng = 0; ng < 2; ng++) {
                unsigned off = sw128((unsigned)((wn * 32 + ng * 16 + rl) * 128) + kb + cl);
                LDSM4(bh[ng], uBh + off);
                LDSM4(bm[ng], uBm + off);
            }
#pragma unroll
            for (int mt = 0; mt < 2; mt++)
#pragma unroll
                for (int nt = 0; nt < 4; nt++) {
                    int ng = nt >> 1, sel = nt & 1;
                    float* acc = c[mt][half * 4 + nt];
                    MMA16816(acc, ah[mt], bh[ng][sel], bh[ng][sel + 2]);
                    MMA16816(acc, ah[mt], bm[ng][sel], bm[ng][sel + 2]);
                    MMA16816(acc, am[mt], bh[ng][sel], bh[ng][sel + 2]);
                }
        }
    };

#pragma unroll 1
    for (int ch = 0; ch < 4; ch++) {
        int k0 = ch * 64;
        __syncthreads();
#pragma unroll
        for (int i = 0; i < 2; i++) {
            int idx = i * 256 + t;
            int r = idx >> 3, c8 = idx & 7;
            unsigned sw = sw128((unsigned)(r * 128 + c8 * 16));
            *(float4*)(sAh + sw) =
                *(const float4*)(Ahi + (size_t)(row0A + r) * HID + k0 + c8 * 8);
            *(float4*)(sAm + sw) =
                *(const float4*)(Amid + (size_t)(row0A + r) * HID + k0 + c8 * 8);
        }
        load_B_half(0, k0);
        __syncthreads();
        compute_half(0);
        __syncthreads();
        load_B_half(1, k0);
        __syncthreads();
        compute_half(1);
    }

    // ---- epilogue ----
    int mwarp = row0A + wm * 32;
    int gc = (lane & 3) * 2;
#pragma unroll
    for (int mt = 0; mt < 2; mt++) {
#pragma unroll
        for (int h = 0; h < 2; h++) {
            int row = mwarp + mt * 16 + (lane >> 2) + h * 8;
            if (MODE == 3) {
                float sa = alpha[row];                      // salpha
                float invc = 1.0f / fmaxf(deg[row], 1.0f);  // cnt
#pragma unroll
                for (int half = 0; half < 2; half++)
#pragma unroll
                    for (int nt = 0; nt < 4; nt++) {
                        int col = half * 128 + wn * 32 + nt * 8 + gc;
                        float2 bb = *(const float2*)(bias + col);
                        float2 xv = *(const float2*)(Cacc + (size_t)row * HID + col);
                        float v0 = (c[mt][half * 4 + nt][h * 2 + 0] + sa * bb.x) * invc + xv.x;
                        float v1 = (c[mt][half * 4 + nt][h * 2 + 1] + sa * bb.y) * invc + xv.y;
                        __nv_bfloat16 h0, m0, h1, m1;
                        split2(v0, h0, m0); split2(v1, h1, m1);
                        *(__nv_bfloat162*)(oh + (size_t)row * HID + col) = __nv_bfloat162(h0, h1);
                        *(__nv_bfloat162*)(om + (size_t)row * HID + col) = __nv_bfloat162(m0, m1);
                    }
            } else {
                float d2 = 0.0f;
                if (SELF) d2 = 1.0f / deg[row];   // deg >= 1 always
#pragma unroll
                for (int half = 0; half < 2; half++)
#pragma unroll
                    for (int nt = 0; nt < 4; nt++) {
                        int col = half * 128 + wn * 32 + nt * 8 + gc;
                        float v0 = c[mt][half * 4 + nt][h * 2 + 0];
                        float v1 = c[mt][half * 4 + nt][h * 2 + 1];
                        if (MODE == 1) {
                            float2 bb = *(const float2*)(bias + col);
                            v0 += bb.x; v1 += bb.y;
                        }
                        *(float2*)(C + (size_t)row * HID + col) = make_float2(v0, v1);
                        if (SELF)
                            *(float2*)(Cacc + (size_t)row * HID + col) =
                                make_float2(v0 * d2, v1 * d2);
                    }
            }
        }
    }
}

// ======== weight prep (all 4 weights in one launch): Bt[n][k]=split(W[k][n]) =
__global__ void k_wprep(const float* __restrict__ Wg1, const float* __restrict__ Wa2f,
                        const float* __restrict__ Wg2, const float* __restrict__ Wf2a,
                        __nv_bfloat16* __restrict__ Bh, __nv_bfloat16* __restrict__ Bm)
{
    int n = blockIdx.x, k = threadIdx.x, w = blockIdx.y;
    const float* W = (w == 0) ? Wg1 : (w == 1) ? Wa2f : (w == 2) ? Wg2 : Wf2a;
    float x = W[k * HID + n];
    __nv_bfloat16 h, m;
    split2(x, h, m);
    Bh[w * HID * HID + n * HID + k] = h;
    Bm[w * HID * HID + n * HID + k] = m;
}

// ================= input projections =========================================
__global__ __launch_bounds__(HID) void k_atom_in(
    const float* __restrict__ x_atom, const float* __restrict__ W1,
    const float* __restrict__ b1, const float* __restrict__ s0,
    __nv_bfloat16* __restrict__ oh, __nv_bfloat16* __restrict__ om,
    float* __restrict__ degA)
{
    __shared__ float xs[FEAT];
    int r = blockIdx.x, h = threadIdx.x;
    if (h < FEAT) xs[h] = x_atom[r * FEAT + h];
    __syncthreads();
    float s = b1[h] + s0[(size_t)r * HID + h];
#pragma unroll
    for (int f = 0; f < FEAT; f++) s += xs[f] * W1[f * HID + h];
    __nv_bfloat16 hi, mi;
    split2(s, hi, mi);
    oh[(size_t)r * HID + h] = hi;
    om[(size_t)r * HID + h] = mi;
    if (h == 0) degA[r] = 1.0f;
}

__global__ __launch_bounds__(HID) void k_frag_in(
    const float* __restrict__ frag_h, const float* __restrict__ W2,
    const float* __restrict__ b2,
    float* __restrict__ xf, float* __restrict__ pooled,
    float* __restrict__ degF, float* __restrict__ cnt,
    float* __restrict__ salpha)
{
    __shared__ float xs[FEAT];
    int r = blockIdx.x, h = threadIdx.x;
    if (h < FEAT) xs[h] = frag_h[r * FEAT + h];
    __syncthreads();
    float s = b2[h];
#pragma unroll
    for (int f = 0; f < FEAT; f++) s += xs[f] * W2[f * HID + h];
    xf[(size_t)r * HID + h] = s;
    pooled[(size_t)r * HID + h] = 0.0f;
    if (h == 0) { degF[r] = 1.0f; cnt[r] = 0.0f; salpha[r] = 0.0f; }
}

// ================= per-frag atom counts (for scatter_mean) ===================
__global__ void k_cnt(const int* __restrict__ a2f, float* __restrict__ cnt, int n)
{
    int i = blockIdx.x * blockDim.x + threadIdx.x;
    if (i < n) atomicAdd(&cnt[a2f[i]], 1.0f);
}

// ================= edge prep =================================================
__global__ void k_edge_prep(const int* __restrict__ ei,
                            const float* __restrict__ raw,
                            float* __restrict__ ew, float* __restrict__ deg, int E)
{
    int e = blockIdx.x * blockDim.x + threadIdx.x;
    if (e >= E) return;
    float w = 1.0f / (1.0f + __expf(raw[e]));
    ew[e] = w;
    atomicAdd(&deg[ei[E + e]], w);
}

__global__ void k_rsqrt(float* __restrict__ deg, int n)
{
    int i = blockIdx.x * blockDim.x + threadIdx.x;
    if (i < n) deg[i] = rsqrtf(deg[i]);
}

// ================= GCN edge scatter (single pass) ============================
__global__ __launch_bounds__(256) void k_scatter(
    const int* __restrict__ ei, const float* __restrict__ ew,
    const float* __restrict__ dinv, const float* __restrict__ xw,
    float* __restrict__ acc, int E)
{
    int e = blockIdx.x * 4 + (threadIdx.x >> 6);
    int j = threadIdx.x & 63;
    if (e >= E) return;
    int s = ei[e], d = ei[E + e];
    float nrm = dinv[s] * ew[e] * dinv[d];
    float4 v = ((const float4*)(xw + (size_t)s * HID))[j];
    v.x *= nrm; v.y *= nrm; v.z *= nrm; v.w *= nrm;
    red_add_v4(acc + (size_t)d * HID + (j << 2), v);
}

// acc = relu(acc + bias); POOL 0: emit split bf16 for next GEMM.
// POOL 1: instead red.add alpha*v into pooled[a2f[row]] and accumulate salpha
//         (split outputs skipped -- nothing consumes them).
template <int POOL>
__global__ void k_bias_relu(float* __restrict__ acc, const float* __restrict__ bias,
                            __nv_bfloat16* __restrict__ oh,
                            __nv_bfloat16* __restrict__ om,
                            const float* __restrict__ alpha,
                            const int* __restrict__ a2f,
                            float* __restrict__ pooled,
                            float* __restrict__ salpha, int n)
{
    int i = blockIdx.x * blockDim.x + threadIdx.x;
    if (i >= n * HID4) return;
    int r = i >> 6;
    float4 v = ((float4*)acc)[i];
    float4 b = ((const float4*)bias)[i & 63];
    v.x = fmaxf(v.x + b.x, 0.f); v.y = fmaxf(v.y + b.y, 0.f);
    v.z = fmaxf(v.z + b.z, 0.f); v.w = fmaxf(v.w + b.w, 0.f);
    ((float4*)acc)[i] = v;
    if (!POOL) {
        __nv_bfloat16 h0, m0, h1, m1, h2, m2, h3, m3;
        split2(v.x, h0, m0); split2(v.y, h1, m1);
        split2(v.z, h2, m2); split2(v.w, h3, m3);
        __nv_bfloat162* ph = (__nv_bfloat162*)(oh + (size_t)i * 4);
        __nv_bfloat162* pm = (__nv_bfloat162*)(om + (size_t)i * 4);
        ph[0] = __nv_bfloat162(h0, h1); ph[1] = __nv_bfloat162(h2, h3);
        pm[0] = __nv_bfloat162(m0, m1); pm[1] = __nv_bfloat162(m2, m3);
    } else {
        float al = alpha[r];
        int f = a2f[r];
        float4 pv = make_float4(v.x * al, v.y * al, v.z * al, v.w * al);
        red_add_v4(pooled + (size_t)f * HID + (i & 63) * 4, pv);
        if ((i & 63) == 0) atomicAdd(&salpha[f], al);
    }
}

// pooled fp32 -> split bf16 (GEMM2' input)
__global__ void k_split_pool(const float* __restrict__ pooled,
                             __nv_bfloat16* __restrict__ oh,
                             __nv_bfloat16* __restrict__ om, int n)
{
    int i = blockIdx.x * blockDim.x + threadIdx.x;
    if (i >= n * HID4) return;
    float4 v = ((const float4*)pooled)[i];
    __nv_bfloat16 h0, m0, h1, m1, h2, m2, h3, m3;
    split2(v.x, h0, m0); split2(v.y, h1, m1);
    split2(v.z, h2, m2); split2(v.w, h3, m3);
    __nv_bfloat162* ph = (__nv_bfloat162*)(oh + (size_t)i * 4);
    __nv_bfloat162* pm = (__nv_bfloat162*)(om + (size_t)i * 4);
    ph[0] = __nv_bfloat162(h0, h1); ph[1] = __nv_bfloat162(h2, h3);
    pm[0] = __nv_bfloat162(m0, m1); pm[1] = __nv_bfloat162(m2, m3);
}

// ================= frag -> atom broadcast ====================================
__global__ __launch_bounds__(256) void k_final(
    const int* __restrict__ a2f, const float* __restrict__ alpha,
    const float* __restrict__ xfp, float* __restrict__ xa, int n)
{
    int a = blockIdx.x * 4 + (threadIdx.x >> 6);
    int j = threadIdx.x & 63;
    if (a >= n) return;
    int f = a2f[a];
    float al = alpha[a];
    float4 v = ((float4*)(xa + (size_t)a * HID))[j];
    float4 p = ((const float4*)(xfp + (size_t)f * HID))[j];
    v.x += p.x * al; v.y += p.y * al; v.z += p.z * al; v.w += p.w * al;
    ((float4*)(xa + (size_t)a * HID))[j] = v;
}

// ================= host orchestration ========================================
extern "C" void kernel_launch(void* const* d_in, const int* in_sizes, int n_in,
                              void* d_out, int out_size)
{
    const float* x_atom  = (const float*)d_in[0];
    const int*   eiA     = (const int*)  d_in[1];
    const float* frag_h  = (const float*)d_in[2];
    const int*   eiF     = (const int*)  d_in[3];
    const int*   a2f     = (const int*)  d_in[4];
    const float* s0      = (const float*)d_in[5];
    const float* alpha   = (const float*)d_in[6];
    const float* curv    = (const float*)d_in[7];
    const float* fewraw  = (const float*)d_in[8];
    const float* W1      = (const float*)d_in[9];
    const float* b1      = (const float*)d_in[10];
    const float* W2      = (const float*)d_in[11];
    const float* b2      = (const float*)d_in[12];
    const float* Wg1     = (const float*)d_in[13];
    const float* bg1     = (const float*)d_in[14];
    const float* Wg2     = (const float*)d_in[15];
    const float* bg2     = (const float*)d_in[16];
    const float* Wa2f    = (const float*)d_in[17];
    const float* ba2f    = (const float*)d_in[18];
    const float* Wf2a    = (const float*)d_in[19];
    const float* bf2a    = (const float*)d_in[20];

    float* out_xa = (float*)d_out;
    float* out_xf = out_xa + (size_t)N_ATOM * HID;

    float *tmpA, *tmpF, *xf, *ewA, *degA, *ewF, *degF, *cnt, *salpha;
    __nv_bfloat16 *ah, *am, *fh, *fm, *ph, *pm, *wth, *wtm;
    cudaGetSymbolAddress((void**)&tmpA, g_tmpA);
    cudaGetSymbolAddress((void**)&tmpF, g_tmpF);
    cudaGetSymbolAddress((void**)&xf,   g_xf);
    cudaGetSymbolAddress((void**)&ewA,  g_ewA);
    cudaGetSymbolAddress((void**)&degA, g_degA);
    cudaGetSymbolAddress((void**)&ewF,  g_ewF);
    cudaGetSymbolAddress((void**)&degF, g_degF);
    cudaGetSymbolAddress((void**)&cnt,  g_cnt);
    cudaGetSymbolAddress((void**)&salpha, g_salpha);
    cudaGetSymbolAddress((void**)&ah,   g_ah);
    cudaGetSymbolAddress((void**)&am,   g_am);
    cudaGetSymbolAddress((void**)&fh,   g_fh);
    cudaGetSymbolAddress((void**)&fm,   g_fm);
    cudaGetSymbolAddress((void**)&ph,   g_ph);
    cudaGetSymbolAddress((void**)&pm,   g_pm);
    cudaGetSymbolAddress((void**)&wth,  g_wth);
    cudaGetSymbolAddress((void**)&wtm,  g_wtm);

    // --- launch order keeps GEMM1 at index 3 (ncu capture) ---
    // 0
    k_wprep<<<dim3(HID, 4), HID>>>(Wg1, Wa2f, Wg2, Wf2a, wth, wtm);
    // 1
    k_atom_in<<<N_ATOM, HID>>>(x_atom, W1, b1, s0, ah, am, degA);
    // 2
    k_edge_prep<<<E_ATOM / 256, 256>>>(eiA, curv, ewA, degA, E_ATOM);
    // 3: atom GCN GEMM [PROFILED]
    gemm_mma<0, 1><<<N_ATOM / 64, 256>>>(
        ah, am, wth, wtm, nullptr, nullptr, degA, nullptr, out_xa, tmpA,
        nullptr, nullptr);
    // 4
    k_rsqrt<<<N_ATOM / 256, 256>>>(degA, N_ATOM);
    // 5: single-pass scatter (R12 form)
    k_scatter<<<E_ATOM / 4, 256>>>(eiA, ewA, degA, tmpA, out_xa, E_ATOM);
    // 6: frag input projection (zeroes pooled/cnt/salpha, seeds degF)
    k_frag_in<<<N_FRAG, HID>>>(frag_h, W2, b2, xf, tmpF, degF, cnt, salpha);
    // 7
    k_cnt<<<N_ATOM / 256, 256>>>(a2f, cnt, N_ATOM);
    // 8: relu+bias AND pooled += alpha * xa_relu (no dead split writes)
    k_bias_relu<1><<<N_ATOM * HID4 / 256, 256>>>(
        out_xa, bg1, nullptr, nullptr, alpha, a2f, tmpF, salpha, N_ATOM);
    // 9: pooled -> split bf16
    k_split_pool<<<N_FRAG * HID4 / 256, 256>>>(tmpF, ph, pm, N_FRAG);
    // 10: frag-sized projection GEMM; epilogue = /cnt + salpha*bias + xf, split
    gemm_mma<3, 0><<<N_FRAG / 64, 256>>>(
        ph, pm, wth + 1 * HID * HID, wtm + 1 * HID * HID, ba2f, salpha,
        cnt, nullptr, xf, nullptr, fh, fm);
    // 11
    k_edge_prep<<<E_FRAG / 256, 256>>>(eiF, fewraw, ewF, degF, E_FRAG);
    // 12: frag GCN GEMM
    gemm_mma<0, 1><<<N_FRAG / 64, 256>>>(
        fh, fm, wth + 2 * HID * HID, wtm + 2 * HID * HID, nullptr, nullptr,
        degF, nullptr, out_xf, tmpF, nullptr, nullptr);
    // 13
    k_rsqrt<<<N_FRAG / 256, 256>>>(degF, N_FRAG);
    // 14
    k_scatter<<<E_FRAG / 4, 256>>>(eiF, ewF, degF, tmpF, out_xf, E_FRAG);
    // 15
    k_bias_relu<0><<<N_FRAG * HID4 / 256, 256>>>(
        out_xf, bg2, fh, fm, nullptr, nullptr, nullptr, nullptr, N_FRAG);
    // 16
    gemm_mma<1, 0><<<N_FRAG / 64, 256>>>(
        fh, fm, wth + 3 * HID * HID, wtm + 3 * HID * HID, bf2a, nullptr,
        nullptr, nullptr, nullptr, tmpF, nullptr, nullptr);
    // 17
    k_final<<<N_ATOM / 4, 256>>>(a2f, alpha, tmpF, out_xa, N_ATOM);
}